// round 1
// baseline (speedup 1.0000x reference)
#include <cuda_runtime.h>
#include <cstdint>
#include <math.h>

#define T_TOK 128
#define HID   2048
#define NEXP  64
#define I2    2816
#define INTER 1408
#define TOPK  8
#define NASSIGN 1024   // T_TOK * TOPK

#define KC 32
#define MT 16

// ---- scratch (device globals; no runtime allocation) ----
__device__ float g_act[NASSIGN * INTER];    // 5.77 MB  activations per assignment
__device__ float g_part[NASSIGN * HID];     // 8.39 MB  per-assignment expert outputs
__device__ float g_gate[NASSIGN];           // renormalized gate weights [t][slot]
__device__ int   g_map[NASSIGN];            // (t,slot) -> assignment id
__device__ int   g_tok[NASSIGN];            // assignment id -> token
__device__ int   g_off[NEXP + 1];           // per-expert offsets (prefix sum)

// =====================================================================
// Routing: softmax -> top-8 -> renorm; build compact per-expert lists.
// Single block, fully deterministic (no atomics).
// =====================================================================
__global__ void routing_kernel(const float* __restrict__ logits) {
    __shared__ float sp[T_TOK][NEXP + 1];
    __shared__ unsigned char schoice[T_TOK][TOPK];
    __shared__ int scnt[NEXP];
    __shared__ int soff[NEXP + 1];

    const int t = threadIdx.x;  // 128 threads, one token each

    float mx = -1e30f;
    #pragma unroll 8
    for (int e = 0; e < NEXP; e++) mx = fmaxf(mx, logits[t * NEXP + e]);
    #pragma unroll 8
    for (int e = 0; e < NEXP; e++) sp[t][e] = expf(logits[t * NEXP + e] - mx);

    float wsel[TOPK];
    int   isel[TOPK];
    for (int s = 0; s < TOPK; s++) {
        float best = -1.f; int bj = 0;
        for (int e = 0; e < NEXP; e++) {
            float v = sp[t][e];
            if (v > best) { best = v; bj = e; }
        }
        wsel[s] = best; isel[s] = bj;
        sp[t][bj] = -2.f;
    }
    float gs = 0.f;
    #pragma unroll
    for (int s = 0; s < TOPK; s++) gs += wsel[s];
    float inv = 1.f / gs;
    #pragma unroll
    for (int s = 0; s < TOPK; s++) {
        schoice[t][s] = (unsigned char)isel[s];
        g_gate[t * TOPK + s] = wsel[s] * inv;
    }
    __syncthreads();

    if (t < NEXP) {
        int c = 0;
        const unsigned char* ch = &schoice[0][0];
        for (int i = 0; i < T_TOK * TOPK; i++) c += (ch[i] == (unsigned char)t);
        scnt[t] = c;
    }
    __syncthreads();
    if (t == 0) {
        int acc = 0;
        for (int e = 0; e < NEXP; e++) { soff[e] = acc; acc += scnt[e]; }
        soff[NEXP] = acc;
        for (int e = 0; e <= NEXP; e++) g_off[e] = soff[e];
    }
    __syncthreads();
    if (t < NEXP) {
        int j = soff[t];
        for (int tok = 0; tok < T_TOK; tok++)
            for (int s = 0; s < TOPK; s++)
                if (schoice[tok][s] == (unsigned char)t) {
                    g_tok[j] = tok;
                    g_map[tok * TOPK + s] = j;
                    j++;
                }
    }
}

// =====================================================================
// Stage 1: act[g, i] = silu(x @ w1_up) * (x @ w1_gate)
// Block: 128 thr; tile = 16 tokens x 128 pairs (256 w1 rows); KC=32.
// Weight tile stored k-major with XOR swizzle: col' = col ^ (4*(k>>2))
//  -> conflict-free smem stores AND conflict-free float4 compute loads.
// =====================================================================
__global__ __launch_bounds__(128, 4)
void stage1_kernel(const float* __restrict__ x, const float* __restrict__ w1) {
    const int e = blockIdx.y, grp = blockIdx.z, ib = blockIdx.x;
    const int off = g_off[e];
    const int cnt = g_off[e + 1] - off;
    const int m0  = grp * MT;
    if (m0 >= cnt) return;
    const int ibase = ib * 128;

    __shared__ float ws[KC * 256];    // 32 KB, k-major swizzled (rows 0..127 up, 128..255 gate)
    __shared__ float xs[MT * 33];     // token tile, m-major padded
    __shared__ int   toks[MT];

    const int tid = threadIdx.x;
    if (tid < MT) toks[tid] = (m0 + tid < cnt) ? g_tok[off + m0 + tid] : -1;

    float hu[4][4], hg[4][4];
    #pragma unroll
    for (int a = 0; a < 4; a++)
        #pragma unroll
        for (int b = 0; b < 4; b++) { hu[a][b] = 0.f; hg[a][b] = 0.f; }

    const int tx = tid & 3;       // token group: tokens 4*tx..4*tx+3
    const int ty = tid >> 2;      // pair group:  pairs 4*ty..4*ty+3
    const float* w1e = w1 + (size_t)e * I2 * HID;
    const int lm = tid >> 3, lc = tid & 7;   // x-tile loader coords

    for (int kc = 0; kc < HID / KC; kc++) {
        __syncthreads();
        // ---- load x tile: 16 x 32 ----
        {
            int tok = toks[lm];
            float4 v = make_float4(0.f, 0.f, 0.f, 0.f);
            if (tok >= 0)
                v = *(const float4*)(x + (size_t)tok * HID + kc * KC + 4 * lc);
            float* d = &xs[lm * 33 + 4 * lc];
            d[0] = v.x; d[1] = v.y; d[2] = v.z; d[3] = v.w;
        }
        // ---- load w tile: 256 rows x 32 k, transpose into k-major swizzled ----
        #pragma unroll 4
        for (int it = 0; it < 16; it++) {
            int f4  = it * 128 + tid;
            int row = f4 >> 3;         // 0..255
            int k4  = f4 & 7;
            int grow = (row < 128) ? (ibase + row) : (INTER + ibase + (row - 128));
            float4 v = *(const float4*)(w1e + (size_t)grow * HID + kc * KC + 4 * k4);
            int col = row ^ (4 * k4);
            ws[(4 * k4 + 0) * 256 + col] = v.x;
            ws[(4 * k4 + 1) * 256 + col] = v.y;
            ws[(4 * k4 + 2) * 256 + col] = v.z;
            ws[(4 * k4 + 3) * 256 + col] = v.w;
        }
        __syncthreads();
        // ---- compute ----
        const float* xb = &xs[4 * tx * 33];
        #pragma unroll 8
        for (int k = 0; k < KC; k++) {
            int sw = k & 28;
            float4 wu = *(const float4*)&ws[k * 256 + ((4 * ty) ^ sw)];
            float4 wg = *(const float4*)&ws[k * 256 + (128 + ((4 * ty) ^ sw))];
            float xv[4];
            #pragma unroll
            for (int mm = 0; mm < 4; mm++) xv[mm] = xb[mm * 33 + k];
            #pragma unroll
            for (int mm = 0; mm < 4; mm++) {
                hu[mm][0] += xv[mm] * wu.x; hu[mm][1] += xv[mm] * wu.y;
                hu[mm][2] += xv[mm] * wu.z; hu[mm][3] += xv[mm] * wu.w;
                hg[mm][0] += xv[mm] * wg.x; hg[mm][1] += xv[mm] * wg.y;
                hg[mm][2] += xv[mm] * wg.z; hg[mm][3] += xv[mm] * wg.w;
            }
        }
    }
    // ---- epilogue: silu(up) * gate ----
    #pragma unroll
    for (int mm = 0; mm < 4; mm++) {
        int m = 4 * tx + mm;
        if (m0 + m < cnt) {
            size_t g = (size_t)(off + m0 + m);
            #pragma unroll
            for (int pp = 0; pp < 4; pp++) {
                float u = hu[mm][pp];
                float a = u / (1.f + expf(-u)) * hg[mm][pp];
                g_act[g * INTER + ibase + 4 * ty + pp] = a;
            }
        }
    }
}

// =====================================================================
// Stage 2: part[g, h] = act[g, :] @ w2[e, h, :]
// Same structure: 16 assignments x 256 h-rows, KC=32 (44 chunks).
// =====================================================================
__global__ __launch_bounds__(128, 4)
void stage2_kernel(const float* __restrict__ w2) {
    const int e = blockIdx.y, grp = blockIdx.z, hb = blockIdx.x;
    const int off = g_off[e];
    const int cnt = g_off[e + 1] - off;
    const int m0  = grp * MT;
    if (m0 >= cnt) return;
    const int hbase = hb * 256;

    __shared__ float ws[KC * 256];
    __shared__ float xs[MT * 33];

    const int tid = threadIdx.x;
    const int tx = tid & 3, ty = tid >> 2;
    const int lm = tid >> 3, lc = tid & 7;

    float a0[4][4], a1[4][4];
    #pragma unroll
    for (int a = 0; a < 4; a++)
        #pragma unroll
        for (int b = 0; b < 4; b++) { a0[a][b] = 0.f; a1[a][b] = 0.f; }

    const float* w2e = w2 + (size_t)e * HID * INTER;
    const bool mvalid = (m0 + lm < cnt);
    const size_t gld = (size_t)(off + m0 + lm);

    for (int kc = 0; kc < INTER / KC; kc++) {
        __syncthreads();
        // ---- act tile ----
        {
            float4 v = make_float4(0.f, 0.f, 0.f, 0.f);
            if (mvalid)
                v = *(const float4*)(g_act + gld * INTER + kc * KC + 4 * lc);
            float* d = &xs[lm * 33 + 4 * lc];
            d[0] = v.x; d[1] = v.y; d[2] = v.z; d[3] = v.w;
        }
        // ---- w2 tile ----
        #pragma unroll 4
        for (int it = 0; it < 16; it++) {
            int f4  = it * 128 + tid;
            int row = f4 >> 3;
            int k4  = f4 & 7;
            float4 v = *(const float4*)(w2e + (size_t)(hbase + row) * INTER + kc * KC + 4 * k4);
            int col = row ^ (4 * k4);
            ws[(4 * k4 + 0) * 256 + col] = v.x;
            ws[(4 * k4 + 1) * 256 + col] = v.y;
            ws[(4 * k4 + 2) * 256 + col] = v.z;
            ws[(4 * k4 + 3) * 256 + col] = v.w;
        }
        __syncthreads();
        const float* xb = &xs[4 * tx * 33];
        #pragma unroll 8
        for (int k = 0; k < KC; k++) {
            int sw = k & 28;
            float4 w0 = *(const float4*)&ws[k * 256 + ((4 * ty) ^ sw)];
            float4 w1v = *(const float4*)&ws[k * 256 + (128 + ((4 * ty) ^ sw))];
            float xv[4];
            #pragma unroll
            for (int mm = 0; mm < 4; mm++) xv[mm] = xb[mm * 33 + k];
            #pragma unroll
            for (int mm = 0; mm < 4; mm++) {
                a0[mm][0] += xv[mm] * w0.x; a0[mm][1] += xv[mm] * w0.y;
                a0[mm][2] += xv[mm] * w0.z; a0[mm][3] += xv[mm] * w0.w;
                a1[mm][0] += xv[mm] * w1v.x; a1[mm][1] += xv[mm] * w1v.y;
                a1[mm][2] += xv[mm] * w1v.z; a1[mm][3] += xv[mm] * w1v.w;
            }
        }
    }
    #pragma unroll
    for (int mm = 0; mm < 4; mm++) {
        int m = 4 * tx + mm;
        if (m0 + m < cnt) {
            size_t g = (size_t)(off + m0 + m);
            #pragma unroll
            for (int pp = 0; pp < 4; pp++) {
                g_part[g * HID + hbase + 4 * ty + pp]       = a0[mm][pp];
                g_part[g * HID + hbase + 128 + 4 * ty + pp] = a1[mm][pp];
            }
        }
    }
}

// =====================================================================
// Combine: out[t, h] = sum_s gate[t,s] * part[map(t,s), h]
// =====================================================================
__global__ void combine_kernel(float* __restrict__ out) {
    const int t   = blockIdx.x;      // 128
    const int tid = threadIdx.x;     // 256
    float4 acc0 = make_float4(0.f, 0.f, 0.f, 0.f);
    float4 acc1 = make_float4(0.f, 0.f, 0.f, 0.f);
    #pragma unroll
    for (int s = 0; s < TOPK; s++) {
        int   g = g_map[t * TOPK + s];
        float w = g_gate[t * TOPK + s];
        const float4* p = (const float4*)(g_part + (size_t)g * HID);
        float4 v0 = p[tid];
        float4 v1 = p[tid + 256];
        acc0.x += w * v0.x; acc0.y += w * v0.y; acc0.z += w * v0.z; acc0.w += w * v0.w;
        acc1.x += w * v1.x; acc1.y += w * v1.y; acc1.z += w * v1.z; acc1.w += w * v1.w;
    }
    float4* o = (float4*)(out + (size_t)t * HID);
    o[tid]       = acc0;
    o[tid + 256] = acc1;
}

// =====================================================================
extern "C" void kernel_launch(void* const* d_in, const int* in_sizes, int n_in,
                              void* d_out, int out_size) {
    (void)in_sizes; (void)n_in; (void)out_size;
    const float* x      = (const float*)d_in[0];
    const float* logits = (const float*)d_in[1];
    const float* w1     = (const float*)d_in[2];
    const float* w2     = (const float*)d_in[3];
    float* out          = (float*)d_out;

    routing_kernel<<<1, T_TOK>>>(logits);
    stage1_kernel<<<dim3(INTER / 128, NEXP, T_TOK * TOPK / (NEXP * MT) * 8), 128>>>(x, w1);
    stage2_kernel<<<dim3(HID / 256, NEXP, 8), 128>>>(w2);
    combine_kernel<<<T_TOK, 256>>>(out);
}

// round 2
// speedup vs baseline: 2.0141x; 2.0141x over previous
#include <cuda_runtime.h>
#include <cstdint>
#include <math.h>

#define T_TOK 128
#define HID   2048
#define NEXP  64
#define I2    2816
#define INTER 1408
#define TOPK  8
#define NASSIGN 1024

#define KC   32          // k per chunk
#define MT   32          // tokens per group (one weight pass per expert)
#define SBS  36          // smem row stride (floats): banks (4g+tg) conflict-free
#define NWARP 4
#define THR  128

#define BUF_FLOATS (256 * SBS + MT * SBS)     // B tile + A tile = 10368
#define BUF_BYTES  (BUF_FLOATS * 4)           // 41472
#define SMEM_BYTES (2 * BUF_BYTES)            // 82944 (double buffered)

// ---- scratch ----
__device__ float g_act[NASSIGN * INTER];
__device__ float g_part[NASSIGN * HID];
__device__ float g_gate[NASSIGN];
__device__ int   g_map[NASSIGN];
__device__ int   g_tok[NASSIGN];
__device__ int   g_off[NEXP + 1];

// =====================================================================
// helpers
// =====================================================================
__device__ __forceinline__ unsigned su32(const void* p) {
    return (unsigned)__cvta_generic_to_shared(p);
}
__device__ __forceinline__ void cp16(unsigned dst, const void* src, int bytes) {
    asm volatile("cp.async.cg.shared.global [%0], [%1], 16, %2;\n"
                 :: "r"(dst), "l"(src), "r"(bytes));
}
__device__ __forceinline__ void cp_commit() { asm volatile("cp.async.commit_group;\n"); }
__device__ __forceinline__ void cp_wait1()  { asm volatile("cp.async.wait_group 1;\n"); }
__device__ __forceinline__ void cp_wait0()  { asm volatile("cp.async.wait_group 0;\n"); }

// round-to-nearest f32 -> tf32 (mantissa bit13 half-up; carry into exp is correct)
__device__ __forceinline__ unsigned rtf(float f) {
    return __float_as_uint(f) + 0x1000u;
}
__device__ __forceinline__ void mma8(float* d,
                                     unsigned a0, unsigned a1, unsigned a2, unsigned a3,
                                     unsigned b0, unsigned b1) {
    asm volatile(
        "mma.sync.aligned.m16n8k8.row.col.f32.tf32.tf32.f32 "
        "{%0,%1,%2,%3}, {%4,%5,%6,%7}, {%8,%9}, {%0,%1,%2,%3};\n"
        : "+f"(d[0]), "+f"(d[1]), "+f"(d[2]), "+f"(d[3])
        : "r"(a0), "r"(a1), "r"(a2), "r"(a3), "r"(b0), "r"(b1));
}

// =====================================================================
// Routing (unchanged; deterministic, single block)
// =====================================================================
__global__ void routing_kernel(const float* __restrict__ logits) {
    __shared__ float sp[T_TOK][NEXP + 1];
    __shared__ unsigned char schoice[T_TOK][TOPK];
    __shared__ int scnt[NEXP];
    __shared__ int soff[NEXP + 1];

    const int t = threadIdx.x;

    float mx = -1e30f;
    #pragma unroll 8
    for (int e = 0; e < NEXP; e++) mx = fmaxf(mx, logits[t * NEXP + e]);
    #pragma unroll 8
    for (int e = 0; e < NEXP; e++) sp[t][e] = expf(logits[t * NEXP + e] - mx);

    float wsel[TOPK]; int isel[TOPK];
    for (int s = 0; s < TOPK; s++) {
        float best = -1.f; int bj = 0;
        for (int e = 0; e < NEXP; e++) {
            float v = sp[t][e];
            if (v > best) { best = v; bj = e; }
        }
        wsel[s] = best; isel[s] = bj; sp[t][bj] = -2.f;
    }
    float gs = 0.f;
    #pragma unroll
    for (int s = 0; s < TOPK; s++) gs += wsel[s];
    float inv = 1.f / gs;
    #pragma unroll
    for (int s = 0; s < TOPK; s++) {
        schoice[t][s] = (unsigned char)isel[s];
        g_gate[t * TOPK + s] = wsel[s] * inv;
    }
    __syncthreads();

    if (t < NEXP) {
        int c = 0;
        const unsigned char* ch = &schoice[0][0];
        for (int i = 0; i < T_TOK * TOPK; i++) c += (ch[i] == (unsigned char)t);
        scnt[t] = c;
    }
    __syncthreads();
    if (t == 0) {
        int acc = 0;
        for (int e = 0; e < NEXP; e++) { soff[e] = acc; acc += scnt[e]; }
        soff[NEXP] = acc;
        for (int e = 0; e <= NEXP; e++) g_off[e] = soff[e];
    }
    __syncthreads();
    if (t < NEXP) {
        int j = soff[t];
        for (int tok = 0; tok < T_TOK; tok++)
            for (int s = 0; s < TOPK; s++)
                if (schoice[tok][s] == (unsigned char)t) {
                    g_tok[j] = tok;
                    g_map[tok * TOPK + s] = j;
                    j++;
                }
    }
}

// =====================================================================
// Stage 1: act = silu(x@w1_up) * (x@w1_gate), tf32 MMA.
// Block: 128 thr (4 warps), tile 32 tokens x 256 cols (interleaved up/gate
// for 128 pairs). Warp w: all 32 m x 64 cols [64w,64w+64).
// =====================================================================
__global__ void __launch_bounds__(THR)
stage1_kernel(const float* __restrict__ x, const float* __restrict__ w1) {
    const int e = blockIdx.y, grp = blockIdx.z, ib = blockIdx.x;
    const int off = g_off[e];
    const int cnt = g_off[e + 1] - off;
    const int m0  = grp * MT;
    if (m0 >= cnt) return;
    const int ibase = ib * 128;          // pair base

    extern __shared__ __align__(16) float dynsm[];
    const unsigned smb = su32(dynsm);

    const int tid  = threadIdx.x;
    const int wid  = tid >> 5, lane = tid & 31;
    const int g    = lane >> 2, tg = lane & 3;
    const int nb   = wid * 64;           // warp col base

    const float* w1e = w1 + (size_t)e * I2 * HID;

    // ---- per-thread load descriptors ----
    // B: 16 slots; A: 2 slots
    const float* bsrc[16];
    unsigned     bdst[16];
    #pragma unroll
    for (int j = 0; j < 16; j++) {
        int idx = j * THR + tid;
        int c = idx >> 3, k4 = idx & 7;
        int p = c >> 1;
        int gr = (c & 1) ? (INTER + ibase + p) : (ibase + p);
        bsrc[j] = w1e + (size_t)gr * HID + k4 * 4;
        bdst[j] = (unsigned)(c * SBS + k4 * 4) * 4u;
    }
    const float* asrc[2];
    int aval[2];
    unsigned adst[2];
    #pragma unroll
    for (int j = 0; j < 2; j++) {
        int idx = j * THR + tid;
        int m = idx >> 3, k4 = idx & 7;
        int valid = (m0 + m) < cnt;
        int tok = valid ? g_tok[off + m0 + m] : 0;
        asrc[j] = x + (size_t)tok * HID + k4 * 4;
        aval[j] = valid ? 16 : 0;
        adst[j] = (unsigned)((256 * SBS) + m * SBS + k4 * 4) * 4u;
    }

    float acc[2][8][4];
    #pragma unroll
    for (int a = 0; a < 2; a++)
        #pragma unroll
        for (int b = 0; b < 8; b++)
            #pragma unroll
            for (int cix = 0; cix < 4; cix++) acc[a][b][cix] = 0.f;

    const int NK = HID / KC;   // 64

    // prologue: chunk 0 -> buffer 0
    {
        #pragma unroll
        for (int j = 0; j < 16; j++) cp16(smb + bdst[j], bsrc[j], 16);
        #pragma unroll
        for (int j = 0; j < 2; j++)  cp16(smb + adst[j], asrc[j], aval[j]);
        cp_commit();
    }

    for (int kc = 0; kc < NK; kc++) {
        const int par = kc & 1;
        if (kc + 1 < NK) {
            const unsigned boff = (par ^ 1) ? (unsigned)BUF_BYTES : 0u;
            const int ko = (kc + 1) * KC;
            #pragma unroll
            for (int j = 0; j < 16; j++) cp16(smb + boff + bdst[j], bsrc[j] + ko, 16);
            #pragma unroll
            for (int j = 0; j < 2; j++)  cp16(smb + boff + adst[j], asrc[j] + ko, aval[j]);
            cp_commit();
            cp_wait1();
        } else {
            cp_wait0();
        }
        __syncthreads();

        const float* bB = dynsm + par * BUF_FLOATS;
        const float* bA = bB + 256 * SBS;

        #pragma unroll
        for (int ks = 0; ks < 4; ks++) {
            unsigned af[2][4];
            #pragma unroll
            for (int mt = 0; mt < 2; mt++) {
                const int r = mt * 16 + g;
                const float* p0 = bA + r * SBS + ks * 8 + tg;
                const float* p1 = bA + (r + 8) * SBS + ks * 8 + tg;
                af[mt][0] = rtf(p0[0]);
                af[mt][1] = rtf(p1[0]);
                af[mt][2] = rtf(p0[4]);
                af[mt][3] = rtf(p1[4]);
            }
            #pragma unroll
            for (int nt = 0; nt < 8; nt++) {
                const float* pb = bB + (nb + nt * 8 + g) * SBS + ks * 8 + tg;
                unsigned b0 = rtf(pb[0]);
                unsigned b1 = rtf(pb[4]);
                mma8(acc[0][nt], af[0][0], af[0][1], af[0][2], af[0][3], b0, b1);
                mma8(acc[1][nt], af[1][0], af[1][1], af[1][2], af[1][3], b0, b1);
            }
        }
        __syncthreads();
    }

    // ---- epilogue: D frag holds (up,gate) adjacent -> silu in-register ----
    #pragma unroll
    for (int mt = 0; mt < 2; mt++) {
        #pragma unroll
        for (int nt = 0; nt < 8; nt++) {
            const int pl = ibase + nb / 2 + nt * 4 + tg;  // pair column
            const int r0 = mt * 16 + g;
            const int r1 = r0 + 8;
            if (m0 + r0 < cnt) {
                float u = acc[mt][nt][0];
                g_act[(size_t)(off + m0 + r0) * INTER + pl] =
                    u / (1.f + expf(-u)) * acc[mt][nt][1];
            }
            if (m0 + r1 < cnt) {
                float u = acc[mt][nt][2];
                g_act[(size_t)(off + m0 + r1) * INTER + pl] =
                    u / (1.f + expf(-u)) * acc[mt][nt][3];
            }
        }
    }
}

// =====================================================================
// Stage 2: part = act @ w2^T, tf32 MMA. Block tile 32 x 256 h-rows.
// =====================================================================
__global__ void __launch_bounds__(THR)
stage2_kernel(const float* __restrict__ w2) {
    const int e = blockIdx.y, grp = blockIdx.z, hb = blockIdx.x;
    const int off = g_off[e];
    const int cnt = g_off[e + 1] - off;
    const int m0  = grp * MT;
    if (m0 >= cnt) return;
    const int hbase = hb * 256;

    extern __shared__ __align__(16) float dynsm[];
    const unsigned smb = su32(dynsm);

    const int tid  = threadIdx.x;
    const int wid  = tid >> 5, lane = tid & 31;
    const int g    = lane >> 2, tg = lane & 3;
    const int nb   = wid * 64;

    const float* w2e = w2 + (size_t)e * HID * INTER;

    const float* bsrc[16];
    unsigned     bdst[16];
    #pragma unroll
    for (int j = 0; j < 16; j++) {
        int idx = j * THR + tid;
        int c = idx >> 3, k4 = idx & 7;
        bsrc[j] = w2e + (size_t)(hbase + c) * INTER + k4 * 4;
        bdst[j] = (unsigned)(c * SBS + k4 * 4) * 4u;
    }
    const float* asrc[2];
    int aval[2];
    unsigned adst[2];
    #pragma unroll
    for (int j = 0; j < 2; j++) {
        int idx = j * THR + tid;
        int m = idx >> 3, k4 = idx & 7;
        int valid = (m0 + m) < cnt;
        asrc[j] = g_act + (size_t)(off + m0 + m) * INTER + k4 * 4;
        aval[j] = valid ? 16 : 0;
        adst[j] = (unsigned)((256 * SBS) + m * SBS + k4 * 4) * 4u;
    }

    float acc[2][8][4];
    #pragma unroll
    for (int a = 0; a < 2; a++)
        #pragma unroll
        for (int b = 0; b < 8; b++)
            #pragma unroll
            for (int cix = 0; cix < 4; cix++) acc[a][b][cix] = 0.f;

    const int NK = INTER / KC;   // 44

    {
        #pragma unroll
        for (int j = 0; j < 16; j++) cp16(smb + bdst[j], bsrc[j], 16);
        #pragma unroll
        for (int j = 0; j < 2; j++)  cp16(smb + adst[j], asrc[j], aval[j]);
        cp_commit();
    }

    for (int kc = 0; kc < NK; kc++) {
        const int par = kc & 1;
        if (kc + 1 < NK) {
            const unsigned boff = (par ^ 1) ? (unsigned)BUF_BYTES : 0u;
            const int ko = (kc + 1) * KC;
            #pragma unroll
            for (int j = 0; j < 16; j++) cp16(smb + boff + bdst[j], bsrc[j] + ko, 16);
            #pragma unroll
            for (int j = 0; j < 2; j++)  cp16(smb + boff + adst[j], asrc[j] + ko, aval[j]);
            cp_commit();
            cp_wait1();
        } else {
            cp_wait0();
        }
        __syncthreads();

        const float* bB = dynsm + par * BUF_FLOATS;
        const float* bA = bB + 256 * SBS;

        #pragma unroll
        for (int ks = 0; ks < 4; ks++) {
            unsigned af[2][4];
            #pragma unroll
            for (int mt = 0; mt < 2; mt++) {
                const int r = mt * 16 + g;
                const float* p0 = bA + r * SBS + ks * 8 + tg;
                const float* p1 = bA + (r + 8) * SBS + ks * 8 + tg;
                af[mt][0] = rtf(p0[0]);
                af[mt][1] = rtf(p1[0]);
                af[mt][2] = rtf(p0[4]);
                af[mt][3] = rtf(p1[4]);
            }
            #pragma unroll
            for (int nt = 0; nt < 8; nt++) {
                const float* pb = bB + (nb + nt * 8 + g) * SBS + ks * 8 + tg;
                unsigned b0 = rtf(pb[0]);
                unsigned b1 = rtf(pb[4]);
                mma8(acc[0][nt], af[0][0], af[0][1], af[0][2], af[0][3], b0, b1);
                mma8(acc[1][nt], af[1][0], af[1][1], af[1][2], af[1][3], b0, b1);
            }
        }
        __syncthreads();
    }

    // ---- epilogue: write partials (float2 per row per ntile) ----
    #pragma unroll
    for (int mt = 0; mt < 2; mt++) {
        #pragma unroll
        for (int nt = 0; nt < 8; nt++) {
            const int col = hbase + nb + nt * 8 + 2 * tg;
            const int r0 = mt * 16 + g;
            const int r1 = r0 + 8;
            if (m0 + r0 < cnt) {
                float2 v = make_float2(acc[mt][nt][0], acc[mt][nt][1]);
                *(float2*)(g_part + (size_t)(off + m0 + r0) * HID + col) = v;
            }
            if (m0 + r1 < cnt) {
                float2 v = make_float2(acc[mt][nt][2], acc[mt][nt][3]);
                *(float2*)(g_part + (size_t)(off + m0 + r1) * HID + col) = v;
            }
        }
    }
}

// =====================================================================
// Combine (unchanged)
// =====================================================================
__global__ void combine_kernel(float* __restrict__ out) {
    const int t   = blockIdx.x;
    const int tid = threadIdx.x;
    float4 acc0 = make_float4(0.f, 0.f, 0.f, 0.f);
    float4 acc1 = make_float4(0.f, 0.f, 0.f, 0.f);
    #pragma unroll
    for (int s = 0; s < TOPK; s++) {
        int   gidx = g_map[t * TOPK + s];
        float w = g_gate[t * TOPK + s];
        const float4* p = (const float4*)(g_part + (size_t)gidx * HID);
        float4 v0 = p[tid];
        float4 v1 = p[tid + 256];
        acc0.x += w * v0.x; acc0.y += w * v0.y; acc0.z += w * v0.z; acc0.w += w * v0.w;
        acc1.x += w * v1.x; acc1.y += w * v1.y; acc1.z += w * v1.z; acc1.w += w * v1.w;
    }
    float4* o = (float4*)(out + (size_t)t * HID);
    o[tid]       = acc0;
    o[tid + 256] = acc1;
}

// =====================================================================
extern "C" void kernel_launch(void* const* d_in, const int* in_sizes, int n_in,
                              void* d_out, int out_size) {
    (void)in_sizes; (void)n_in; (void)out_size;
    const float* x      = (const float*)d_in[0];
    const float* logits = (const float*)d_in[1];
    const float* w1     = (const float*)d_in[2];
    const float* w2     = (const float*)d_in[3];
    float* out          = (float*)d_out;

    cudaFuncSetAttribute(stage1_kernel,
                         cudaFuncAttributeMaxDynamicSharedMemorySize, SMEM_BYTES);
    cudaFuncSetAttribute(stage2_kernel,
                         cudaFuncAttributeMaxDynamicSharedMemorySize, SMEM_BYTES);

    routing_kernel<<<1, T_TOK>>>(logits);
    stage1_kernel<<<dim3(INTER / 128, NEXP, 3), THR, SMEM_BYTES>>>(x, w1);
    stage2_kernel<<<dim3(HID / 256, NEXP, 3), THR, SMEM_BYTES>>>(w2);
    combine_kernel<<<T_TOK, 256>>>(out);
}

// round 3
// speedup vs baseline: 2.4319x; 1.2074x over previous
#include <cuda_runtime.h>
#include <cstdint>
#include <math.h>

#define T_TOK 128
#define HID   2048
#define NEXP  64
#define I2    2816
#define INTER 1408
#define TOPK  8
#define NASSIGN 1024

#define KC   32
#define MT   32
#define SBS  36
#define THR  128

#define S1_BLOCKS (NEXP * 11)          // 704 : (e, ib) ib<11, 128 pairs each
#define S2_BLOCKS (NEXP * 8)           // 512 : (e, hb) hb<8, 256 h-rows each
#define CMB_BLOCKS T_TOK               // 128
#define TOTAL_BLOCKS (S1_BLOCKS + S2_BLOCKS + CMB_BLOCKS)   // 1344

#define BUF_FLOATS (256 * SBS + MT * SBS)
#define BUF_BYTES  (BUF_FLOATS * 4)
#define SMEM_BYTES (2 * BUF_BYTES)     // 82944

// ---- scratch ----
__device__ float g_act[NASSIGN * INTER];
__device__ float g_part[NASSIGN * HID];
__device__ float g_gate[NASSIGN];
__device__ int   g_map[NASSIGN];
__device__ int   g_tok[NASSIGN];
__device__ int   g_off[NEXP + 1];
__device__ int   g_s1done[NEXP];
__device__ int   g_s2done;

// =====================================================================
// helpers
// =====================================================================
__device__ __forceinline__ unsigned su32(const void* p) {
    return (unsigned)__cvta_generic_to_shared(p);
}
__device__ __forceinline__ void cp16(unsigned dst, const void* src, int bytes) {
    asm volatile("cp.async.cg.shared.global [%0], [%1], 16, %2;\n"
                 :: "r"(dst), "l"(src), "r"(bytes));
}
__device__ __forceinline__ void cp_commit() { asm volatile("cp.async.commit_group;\n"); }
__device__ __forceinline__ void cp_wait1()  { asm volatile("cp.async.wait_group 1;\n"); }
__device__ __forceinline__ void cp_wait0()  { asm volatile("cp.async.wait_group 0;\n"); }

__device__ __forceinline__ unsigned rtf(float f) {   // f32 -> tf32 round-to-nearest
    return __float_as_uint(f) + 0x1000u;
}
__device__ __forceinline__ void mma8(float* d,
                                     unsigned a0, unsigned a1, unsigned a2, unsigned a3,
                                     unsigned b0, unsigned b1) {
    asm volatile(
        "mma.sync.aligned.m16n8k8.row.col.f32.tf32.tf32.f32 "
        "{%0,%1,%2,%3}, {%4,%5,%6,%7}, {%8,%9}, {%0,%1,%2,%3};\n"
        : "+f"(d[0]), "+f"(d[1]), "+f"(d[2]), "+f"(d[3])
        : "r"(a0), "r"(a1), "r"(a2), "r"(a3), "r"(b0), "r"(b1));
}

__device__ __forceinline__ void spin_until(volatile int* p, int need) {
    while (*p < need) __nanosleep(128);
}

// =====================================================================
// Routing + flag reset (single block, deterministic)
// =====================================================================
__global__ void routing_kernel(const float* __restrict__ logits) {
    __shared__ float sp[T_TOK][NEXP + 1];
    __shared__ unsigned char schoice[T_TOK][TOPK];
    __shared__ int scnt[NEXP];
    __shared__ int soff[NEXP + 1];

    const int t = threadIdx.x;

    // reset dependency flags for this launch
    if (t < NEXP) g_s1done[t] = 0;
    if (t == 0)   g_s2done = 0;

    float mx = -1e30f;
    #pragma unroll 8
    for (int e = 0; e < NEXP; e++) mx = fmaxf(mx, logits[t * NEXP + e]);
    #pragma unroll 8
    for (int e = 0; e < NEXP; e++) sp[t][e] = expf(logits[t * NEXP + e] - mx);

    float wsel[TOPK]; int isel[TOPK];
    for (int s = 0; s < TOPK; s++) {
        float best = -1.f; int bj = 0;
        for (int e = 0; e < NEXP; e++) {
            float v = sp[t][e];
            if (v > best) { best = v; bj = e; }
        }
        wsel[s] = best; isel[s] = bj; sp[t][bj] = -2.f;
    }
    float gs = 0.f;
    #pragma unroll
    for (int s = 0; s < TOPK; s++) gs += wsel[s];
    float inv = 1.f / gs;
    #pragma unroll
    for (int s = 0; s < TOPK; s++) {
        schoice[t][s] = (unsigned char)isel[s];
        g_gate[t * TOPK + s] = wsel[s] * inv;
    }
    __syncthreads();

    if (t < NEXP) {
        int c = 0;
        const unsigned char* ch = &schoice[0][0];
        for (int i = 0; i < T_TOK * TOPK; i++) c += (ch[i] == (unsigned char)t);
        scnt[t] = c;
    }
    __syncthreads();
    if (t == 0) {
        int acc = 0;
        for (int e = 0; e < NEXP; e++) { soff[e] = acc; acc += scnt[e]; }
        soff[NEXP] = acc;
        for (int e = 0; e <= NEXP; e++) g_off[e] = soff[e];
    }
    __syncthreads();
    if (t < NEXP) {
        int j = soff[t];
        for (int tok = 0; tok < T_TOK; tok++)
            for (int s = 0; s < TOPK; s++)
                if (schoice[tok][s] == (unsigned char)t) {
                    g_tok[j] = tok;
                    g_map[tok * TOPK + s] = j;
                    j++;
                }
    }
}

// =====================================================================
// Fused MoE kernel: bids [0,704) stage1, [704,1216) stage2, [1216,1344) combine
// =====================================================================
__global__ void __launch_bounds__(THR)
moe_kernel(const float* __restrict__ x, const float* __restrict__ w1,
           const float* __restrict__ w2, float* __restrict__ out) {
    extern __shared__ __align__(16) float dynsm[];
    const unsigned smb = su32(dynsm);

    const int bid = blockIdx.x;
    const int tid = threadIdx.x;
    const int wid = tid >> 5, lane = tid & 31;
    const int g   = lane >> 2, tg = lane & 3;
    const int nb  = wid * 64;

    // =========================== STAGE 1 ===========================
    if (bid < S1_BLOCKS) {
        const int e  = bid / 11;
        const int ib = bid % 11;
        const int off = g_off[e];
        const int cnt = g_off[e + 1] - off;
        const int ibase = ib * 128;
        const int ngrp = (cnt + MT - 1) / MT;
        const float* w1e = w1 + (size_t)e * I2 * HID;

        __shared__ int toks[MT];

        // B load descriptors are group-invariant
        const float* bsrc[16];
        unsigned     bdst[16];
        #pragma unroll
        for (int j = 0; j < 16; j++) {
            int idx = j * THR + tid;
            int c = idx >> 3, k4 = idx & 7;
            int p = c >> 1;
            int gr = (c & 1) ? (INTER + ibase + p) : (ibase + p);
            bsrc[j] = w1e + (size_t)gr * HID + k4 * 4;
            bdst[j] = (unsigned)(c * SBS + k4 * 4) * 4u;
        }

        for (int grp = 0; grp < ngrp; grp++) {
            const int m0 = grp * MT;
            if (tid < MT) toks[tid] = (m0 + tid < cnt) ? g_tok[off + m0 + tid] : -1;
            __syncthreads();

            const float* asrc[2];
            int aval[2];
            unsigned adst[2];
            #pragma unroll
            for (int j = 0; j < 2; j++) {
                int idx = j * THR + tid;
                int m = idx >> 3, k4 = idx & 7;
                int tok = toks[m];
                asrc[j] = x + (size_t)(tok < 0 ? 0 : tok) * HID + k4 * 4;
                aval[j] = (tok >= 0) ? 16 : 0;
                adst[j] = (unsigned)((256 * SBS) + m * SBS + k4 * 4) * 4u;
            }

            float acc[2][8][4];
            #pragma unroll
            for (int a = 0; a < 2; a++)
                #pragma unroll
                for (int b = 0; b < 8; b++)
                    #pragma unroll
                    for (int cix = 0; cix < 4; cix++) acc[a][b][cix] = 0.f;

            const int NK = HID / KC;   // 64
            #pragma unroll
            for (int j = 0; j < 16; j++) cp16(smb + bdst[j], bsrc[j], 16);
            #pragma unroll
            for (int j = 0; j < 2; j++)  cp16(smb + adst[j], asrc[j], aval[j]);
            cp_commit();

            for (int kc = 0; kc < NK; kc++) {
                const int par = kc & 1;
                if (kc + 1 < NK) {
                    const unsigned boff = (par ^ 1) ? (unsigned)BUF_BYTES : 0u;
                    const int ko = (kc + 1) * KC;
                    #pragma unroll
                    for (int j = 0; j < 16; j++) cp16(smb + boff + bdst[j], bsrc[j] + ko, 16);
                    #pragma unroll
                    for (int j = 0; j < 2; j++)  cp16(smb + boff + adst[j], asrc[j] + ko, aval[j]);
                    cp_commit();
                    cp_wait1();
                } else {
                    cp_wait0();
                }
                __syncthreads();

                const float* bB = dynsm + par * BUF_FLOATS;
                const float* bA = bB + 256 * SBS;

                #pragma unroll
                for (int ks = 0; ks < 4; ks++) {
                    unsigned af[2][4];
                    #pragma unroll
                    for (int mt = 0; mt < 2; mt++) {
                        const int r = mt * 16 + g;
                        const float* p0 = bA + r * SBS + ks * 8 + tg;
                        const float* p1 = bA + (r + 8) * SBS + ks * 8 + tg;
                        af[mt][0] = rtf(p0[0]);
                        af[mt][1] = rtf(p1[0]);
                        af[mt][2] = rtf(p0[4]);
                        af[mt][3] = rtf(p1[4]);
                    }
                    #pragma unroll
                    for (int nt = 0; nt < 8; nt++) {
                        const float* pb = bB + (nb + nt * 8 + g) * SBS + ks * 8 + tg;
                        unsigned b0 = rtf(pb[0]);
                        unsigned b1 = rtf(pb[4]);
                        mma8(acc[0][nt], af[0][0], af[0][1], af[0][2], af[0][3], b0, b1);
                        mma8(acc[1][nt], af[1][0], af[1][1], af[1][2], af[1][3], b0, b1);
                    }
                }
                __syncthreads();
            }

            // epilogue: silu(up)*gate, pair interleave keeps both in-thread
            #pragma unroll
            for (int mt = 0; mt < 2; mt++) {
                #pragma unroll
                for (int nt = 0; nt < 8; nt++) {
                    const int pl = ibase + nb / 2 + nt * 4 + tg;
                    const int r0 = mt * 16 + g;
                    const int r1 = r0 + 8;
                    if (m0 + r0 < cnt) {
                        float u = acc[mt][nt][0];
                        g_act[(size_t)(off + m0 + r0) * INTER + pl] =
                            u / (1.f + expf(-u)) * acc[mt][nt][1];
                    }
                    if (m0 + r1 < cnt) {
                        float u = acc[mt][nt][2];
                        g_act[(size_t)(off + m0 + r1) * INTER + pl] =
                            u / (1.f + expf(-u)) * acc[mt][nt][3];
                    }
                }
            }
            __syncthreads();
        }

        __syncthreads();
        if (tid == 0) {
            __threadfence();
            atomicAdd(&g_s1done[e], 1);
        }
        return;
    }

    // =========================== STAGE 2 ===========================
    if (bid < S1_BLOCKS + S2_BLOCKS) {
        const int sb = bid - S1_BLOCKS;
        const int e  = sb / 8;
        const int hb = sb % 8;
        const int off = g_off[e];
        const int cnt = g_off[e + 1] - off;
        const int hbase = hb * 256;
        const int ngrp = (cnt + MT - 1) / MT;
        const float* w2e = w2 + (size_t)e * HID * INTER;

        // wait for this expert's activations
        if (tid == 0) {
            spin_until(&g_s1done[e], 11);
            __threadfence();
        }
        __syncthreads();

        const float* bsrc[16];
        unsigned     bdst[16];
        #pragma unroll
        for (int j = 0; j < 16; j++) {
            int idx = j * THR + tid;
            int c = idx >> 3, k4 = idx & 7;
            bsrc[j] = w2e + (size_t)(hbase + c) * INTER + k4 * 4;
            bdst[j] = (unsigned)(c * SBS + k4 * 4) * 4u;
        }

        for (int grp = 0; grp < ngrp; grp++) {
            const int m0 = grp * MT;

            const float* asrc[2];
            int aval[2];
            unsigned adst[2];
            #pragma unroll
            for (int j = 0; j < 2; j++) {
                int idx = j * THR + tid;
                int m = idx >> 3, k4 = idx & 7;
                int valid = (m0 + m) < cnt;
                asrc[j] = g_act + (size_t)(off + (valid ? m0 + m : 0)) * INTER + k4 * 4;
                aval[j] = valid ? 16 : 0;
                adst[j] = (unsigned)((256 * SBS) + m * SBS + k4 * 4) * 4u;
            }

            float acc[2][8][4];
            #pragma unroll
            for (int a = 0; a < 2; a++)
                #pragma unroll
                for (int b = 0; b < 8; b++)
                    #pragma unroll
                    for (int cix = 0; cix < 4; cix++) acc[a][b][cix] = 0.f;

            const int NK = INTER / KC;   // 44
            #pragma unroll
            for (int j = 0; j < 16; j++) cp16(smb + bdst[j], bsrc[j], 16);
            #pragma unroll
            for (int j = 0; j < 2; j++)  cp16(smb + adst[j], asrc[j], aval[j]);
            cp_commit();

            for (int kc = 0; kc < NK; kc++) {
                const int par = kc & 1;
                if (kc + 1 < NK) {
                    const unsigned boff = (par ^ 1) ? (unsigned)BUF_BYTES : 0u;
                    const int ko = (kc + 1) * KC;
                    #pragma unroll
                    for (int j = 0; j < 16; j++) cp16(smb + boff + bdst[j], bsrc[j] + ko, 16);
                    #pragma unroll
                    for (int j = 0; j < 2; j++)  cp16(smb + boff + adst[j], asrc[j] + ko, aval[j]);
                    cp_commit();
                    cp_wait1();
                } else {
                    cp_wait0();
                }
                __syncthreads();

                const float* bB = dynsm + par * BUF_FLOATS;
                const float* bA = bB + 256 * SBS;

                #pragma unroll
                for (int ks = 0; ks < 4; ks++) {
                    unsigned af[2][4];
                    #pragma unroll
                    for (int mt = 0; mt < 2; mt++) {
                        const int r = mt * 16 + g;
                        const float* p0 = bA + r * SBS + ks * 8 + tg;
                        const float* p1 = bA + (r + 8) * SBS + ks * 8 + tg;
                        af[mt][0] = rtf(p0[0]);
                        af[mt][1] = rtf(p1[0]);
                        af[mt][2] = rtf(p0[4]);
                        af[mt][3] = rtf(p1[4]);
                    }
                    #pragma unroll
                    for (int nt = 0; nt < 8; nt++) {
                        const float* pb = bB + (nb + nt * 8 + g) * SBS + ks * 8 + tg;
                        unsigned b0 = rtf(pb[0]);
                        unsigned b1 = rtf(pb[4]);
                        mma8(acc[0][nt], af[0][0], af[0][1], af[0][2], af[0][3], b0, b1);
                        mma8(acc[1][nt], af[1][0], af[1][1], af[1][2], af[1][3], b0, b1);
                    }
                }
                __syncthreads();
            }

            #pragma unroll
            for (int mt = 0; mt < 2; mt++) {
                #pragma unroll
                for (int nt = 0; nt < 8; nt++) {
                    const int col = hbase + nb + nt * 8 + 2 * tg;
                    const int r0 = mt * 16 + g;
                    const int r1 = r0 + 8;
                    if (m0 + r0 < cnt) {
                        float2 v = make_float2(acc[mt][nt][0], acc[mt][nt][1]);
                        *(float2*)(g_part + (size_t)(off + m0 + r0) * HID + col) = v;
                    }
                    if (m0 + r1 < cnt) {
                        float2 v = make_float2(acc[mt][nt][2], acc[mt][nt][3]);
                        *(float2*)(g_part + (size_t)(off + m0 + r1) * HID + col) = v;
                    }
                }
            }
            __syncthreads();
        }

        __syncthreads();
        if (tid == 0) {
            __threadfence();
            atomicAdd(&g_s2done, 1);
        }
        return;
    }

    // =========================== COMBINE ===========================
    {
        const int t = bid - (S1_BLOCKS + S2_BLOCKS);
        if (tid == 0) {
            spin_until(&g_s2done, S2_BLOCKS);
            __threadfence();
        }
        __syncthreads();

        int   gi[TOPK];
        float gw[TOPK];
        #pragma unroll
        for (int s = 0; s < TOPK; s++) {
            gi[s] = g_map[t * TOPK + s];
            gw[s] = g_gate[t * TOPK + s];
        }
        #pragma unroll
        for (int j = 0; j < 4; j++) {
            const int c4 = tid + j * THR;      // float4 index within row
            float4 acc = make_float4(0.f, 0.f, 0.f, 0.f);
            #pragma unroll
            for (int s = 0; s < TOPK; s++) {
                const float4 v = *(const float4*)(g_part + (size_t)gi[s] * HID + 4 * c4);
                const float w = gw[s];
                acc.x += w * v.x; acc.y += w * v.y;
                acc.z += w * v.z; acc.w += w * v.w;
            }
            *(float4*)(out + (size_t)t * HID + 4 * c4) = acc;
        }
    }
}

// =====================================================================
extern "C" void kernel_launch(void* const* d_in, const int* in_sizes, int n_in,
                              void* d_out, int out_size) {
    (void)in_sizes; (void)n_in; (void)out_size;
    const float* x      = (const float*)d_in[0];
    const float* logits = (const float*)d_in[1];
    const float* w1     = (const float*)d_in[2];
    const float* w2     = (const float*)d_in[3];
    float* out          = (float*)d_out;

    static int configured = 0;
    if (!configured) {
        cudaFuncSetAttribute(moe_kernel,
                             cudaFuncAttributeMaxDynamicSharedMemorySize, SMEM_BYTES);
        configured = 1;
    }

    routing_kernel<<<1, T_TOK>>>(logits);
    moe_kernel<<<TOTAL_BLOCKS, THR, SMEM_BYTES>>>(x, w1, w2, out);
}